// round 6
// baseline (speedup 1.0000x reference)
#include <cuda_runtime.h>
#include <cuda_bf16.h>
#include <cstdint>

// Problem constants (fixed by the dataset)
#define D_ATOM 256
#define D_EDGE 256
#define D_CAT  768          // 2*D_EDGE + D_ATOM
#define D_X12  512          // x1|x2 region only (h read directly by GEMM)
#define MAX_ATOMS 100000

// Scratch: x12 = [x1 | x2], row-major, ld = 512. (204.8 MB)
__device__ float g_x12[(size_t)MAX_ATOMS * D_X12];
// W transposed + split into bf16 hi/lo: Wt[n][k] = W[k][n]
__device__ __nv_bfloat16 g_Wt_hi[256 * 768];
__device__ __nv_bfloat16 g_Wt_lo[256 * 768];

// ============================================================================
// small PTX helpers (all legal on compute_103 / sm_80+)
// ============================================================================
__device__ __forceinline__ uint32_t smem_u32(const void* p) {
    uint32_t a;
    asm("{ .reg .u64 t; cvta.to.shared.u64 t, %1; cvt.u32.u64 %0, t; }"
        : "=r"(a) : "l"(p));
    return a;
}
__device__ __forceinline__ uint32_t lds32(uint32_t a) {
    uint32_t v;
    asm volatile("ld.shared.b32 %0, [%1];" : "=r"(v) : "r"(a));
    return v;
}
__device__ __forceinline__ void sts64(uint32_t a, uint32_t x, uint32_t y) {
    asm volatile("st.shared.v2.b32 [%0], {%1, %2};" :: "r"(a), "r"(x), "r"(y) : "memory");
}
#define CP_ASYNC_16(saddr, gptr) \
    asm volatile("cp.async.cg.shared.global [%0], [%1], 16;" \
                 :: "r"(saddr), "l"(gptr) : "memory")
#define CP_ASYNC_COMMIT() asm volatile("cp.async.commit_group;" ::: "memory")
#define CP_ASYNC_WAIT0()  asm volatile("cp.async.wait_group 0;" ::: "memory")

// bf16 MMA: D(16x8,f32) += A(16x16,bf16,row) * B(16x8,bf16,col)
__device__ __forceinline__ void mma16816(float* c, const uint32_t* a, const uint32_t* b) {
    asm volatile(
        "mma.sync.aligned.m16n8k16.row.col.f32.bf16.bf16.f32 "
        "{%0,%1,%2,%3}, {%4,%5,%6,%7}, {%8,%9}, {%0,%1,%2,%3};"
        : "+f"(c[0]), "+f"(c[1]), "+f"(c[2]), "+f"(c[3])
        : "r"(a[0]), "r"(a[1]), "r"(a[2]), "r"(a[3]), "r"(b[0]), "r"(b[1]));
}

// 32-byte streaming load with evict_first (ptxas requires v8.b32 for this hint)
__device__ __forceinline__ void ldg_stream_v8(const float* p, float4& a, float4& b) {
    uint32_t r0, r1, r2, r3, r4, r5, r6, r7;
    asm volatile(
        "ld.global.nc.L2::evict_first.v8.b32 {%0,%1,%2,%3,%4,%5,%6,%7}, [%8];"
        : "=r"(r0), "=r"(r1), "=r"(r2), "=r"(r3),
          "=r"(r4), "=r"(r5), "=r"(r6), "=r"(r7)
        : "l"(p));
    a = make_float4(__uint_as_float(r0), __uint_as_float(r1),
                    __uint_as_float(r2), __uint_as_float(r3));
    b = make_float4(__uint_as_float(r4), __uint_as_float(r5),
                    __uint_as_float(r6), __uint_as_float(r7));
}

// ---------------------------------------------------------------------------
// Kernel 1: zero the x12 scratch (atomic targets).
// ---------------------------------------------------------------------------
__global__ void init_x12_kernel(int nAtoms) {
    size_t gid = (size_t)blockIdx.x * blockDim.x + threadIdx.x;
    size_t total = (size_t)nAtoms * (D_X12 / 4);
    if (gid >= total) return;
    *(float4*)(g_x12 + gid * 4) = make_float4(0.f, 0.f, 0.f, 0.f);
}

// ---------------------------------------------------------------------------
// Kernel 2: scatter, destination-tiled so each pass's target region
// (atoms [lo,hi), 512 floats/atom = 102.4 MB per half) is L2-resident
// => atomics never RMW DRAM. 32 threads per edge (one 8-float chunk each);
// predicates are uniform per edge => no intra-warp divergence within a half-warp.
// ---------------------------------------------------------------------------
__device__ __forceinline__ void red_add_v4(float* addr, float4 v) {
    asm volatile("red.global.add.v4.f32 [%0], {%1, %2, %3, %4};"
                 :: "l"(addr), "f"(v.x), "f"(v.y), "f"(v.z), "f"(v.w)
                 : "memory");
}

__global__ void scatter_half_kernel(const float* __restrict__ m1,
                                    const float* __restrict__ m2,
                                    const int* __restrict__ id1,
                                    const int* __restrict__ id2,
                                    const int* __restrict__ id3,
                                    const int* __restrict__ id4,
                                    int nEdges, int lo, int hi) {
    size_t gid = (size_t)blockIdx.x * blockDim.x + threadIdx.x;
    size_t total = (size_t)nEdges * 32;
    if (gid >= total) return;
    int e = (int)(gid >> 5);
    int c = (int)(gid & 31);
    size_t coff = (size_t)c * 8;

    int i1 = __ldg(id1 + e);
    int i3 = __ldg(id3 + e);
    bool a1 = (i1 >= lo) & (i1 < hi);
    bool a3 = (i3 >= lo) & (i3 < hi);
    if (a1 | a3) {
        float4 va, vb;
        ldg_stream_v8(m1 + (size_t)e * D_EDGE + coff, va, vb);
        if (a1) {
            float* d = g_x12 + (size_t)i1 * D_X12 + coff;
            red_add_v4(d, va);
            red_add_v4(d + 4, vb);
        }
        if (a3) {
            float* d = g_x12 + (size_t)i3 * D_X12 + coff;
            red_add_v4(d,     make_float4(-va.x, -va.y, -va.z, -va.w));
            red_add_v4(d + 4, make_float4(-vb.x, -vb.y, -vb.z, -vb.w));
        }
    }

    int i2 = __ldg(id2 + e);
    int i4 = __ldg(id4 + e);
    bool a2 = (i2 >= lo) & (i2 < hi);
    bool a4 = (i4 >= lo) & (i4 < hi);
    if (a2 | a4) {
        float4 va, vb;
        ldg_stream_v8(m2 + (size_t)e * D_EDGE + coff, va, vb);
        if (a2) {
            float* d = g_x12 + (size_t)i2 * D_X12 + 256 + coff;
            red_add_v4(d, va);
            red_add_v4(d + 4, vb);
        }
        if (a4) {
            float* d = g_x12 + (size_t)i4 * D_X12 + 256 + coff;
            red_add_v4(d,     make_float4(-va.x, -va.y, -va.z, -va.w));
            red_add_v4(d + 4, make_float4(-vb.x, -vb.y, -vb.z, -vb.w));
        }
    }
}

// ---------------------------------------------------------------------------
// Kernel 3: transpose + bf16-split W.  Wt[n][k] = W[k][n] -> (hi, lo) bf16.
// ---------------------------------------------------------------------------
__global__ void prep_w_kernel(const float* __restrict__ W) {
    int gid = blockIdx.x * blockDim.x + threadIdx.x;
    if (gid >= 256 * 768) return;
    int n = gid / 768;
    int k = gid % 768;
    float w = W[(size_t)k * 256 + n];
    __nv_bfloat16 hi = __float2bfloat16_rn(w);
    __nv_bfloat16 lo = __float2bfloat16_rn(w - __bfloat162float(hi));
    g_Wt_hi[gid] = hi;
    g_Wt_lo[gid] = lo;
}

// ---------------------------------------------------------------------------
// Kernel 4: mma.sync bf16 split-3 GEMM:
//   C[M,256] = [x12 | h][M,768] @ W[768,256]
//   CTA: M-tile 128 x full N=256, 512 threads (16 warps, 4x4).
//   Warp tile 32(M) x 64(N). K-tiles of 32, double-buffered SMEM.
//   Per K-tile, 3 products: Ahi*Bhi, Ahi*Blo, Alo*Bhi (fp32 accum).
// ---------------------------------------------------------------------------
#define BK 32
#define ROWB 80                       // smem row stride bytes (64B data + 16 pad)
#define OFF_A_HI 0
#define OFF_A_LO 10240                // 128*80
#define OFF_B_HI 20480
#define OFF_B_LO 40960                // +256*80
#define BUF_BYTES 61440
#define GEMM_SMEM (2 * BUF_BYTES)     // 122880

__device__ __forceinline__ void split2(float a, float b, uint32_t& hi, uint32_t& lo) {
    __nv_bfloat16 ha = __float2bfloat16_rn(a);
    __nv_bfloat16 hb = __float2bfloat16_rn(b);
    __nv_bfloat16 la = __float2bfloat16_rn(a - __bfloat162float(ha));
    __nv_bfloat16 lb = __float2bfloat16_rn(b - __bfloat162float(hb));
    hi = (uint32_t)__bfloat16_as_ushort(ha) | ((uint32_t)__bfloat16_as_ushort(hb) << 16);
    lo = (uint32_t)__bfloat16_as_ushort(la) | ((uint32_t)__bfloat16_as_ushort(lb) << 16);
}

__global__ __launch_bounds__(512, 1)
void gemm_mma_kernel(const float* __restrict__ h, float* __restrict__ C, int M) {
    extern __shared__ char smem[];
    const uint32_t sbase = smem_u32(smem);

    const int tid = threadIdx.x;
    const int wid = tid >> 5;
    const int lid = tid & 31;
    const int wm = wid >> 2;          // 0..3  (M group of 32 rows)
    const int wn = wid & 3;           // 0..3  (N group of 64 cols)
    const int g = lid >> 2;           // 0..7
    const int q = lid & 3;            // 0..3
    const int bm = blockIdx.x * 128;

    float acc[2][8][4];
    #pragma unroll
    for (int i = 0; i < 2; i++)
        #pragma unroll
        for (int j = 0; j < 8; j++)
            #pragma unroll
            for (int r = 0; r < 4; r++) acc[i][j][r] = 0.f;

    auto issue_B = [&](uint32_t dstbuf, int k0) {
        #pragma unroll
        for (int it = 0; it < 4; it++) {
            int idx = tid + it * 512;
            int hf = idx >> 10;
            int n = (idx >> 2) & 255;
            int f = idx & 3;
            const __nv_bfloat16* src = (hf ? g_Wt_lo : g_Wt_hi) + (size_t)n * D_CAT + k0 + f * 8;
            uint32_t dst = dstbuf + (hf ? OFF_B_LO : OFF_B_HI) + n * ROWB + f * 16;
            CP_ASYNC_16(dst, src);
        }
    };
    auto ldg_A = [&](float4* av, int k0) {
        #pragma unroll
        for (int it = 0; it < 2; it++) {
            int idx = tid + it * 512;
            int m = idx >> 3;
            int f = idx & 7;
            int gm = bm + m;
            float4 v = make_float4(0.f, 0.f, 0.f, 0.f);
            if (gm < M) {
                if (k0 < D_X12)
                    v = *(const float4*)(g_x12 + (size_t)gm * D_X12 + k0 + f * 4);
                else
                    v = *(const float4*)(h + (size_t)gm * D_ATOM + (k0 - D_X12) + f * 4);
            }
            av[it] = v;
        }
    };
    auto sts_A = [&](uint32_t dstbuf, const float4* av) {
        #pragma unroll
        for (int it = 0; it < 2; it++) {
            int idx = tid + it * 512;
            int m = idx >> 3;
            int f = idx & 7;
            uint32_t h0, l0, h1, l1;
            split2(av[it].x, av[it].y, h0, l0);
            split2(av[it].z, av[it].w, h1, l1);
            uint32_t off = m * ROWB + f * 8;
            sts64(dstbuf + OFF_A_HI + off, h0, h1);
            sts64(dstbuf + OFF_A_LO + off, l0, l1);
        }
    };

    // ---- prologue: tile 0 ----
    {
        float4 av[2];
        issue_B(sbase, 0);
        CP_ASYNC_COMMIT();
        ldg_A(av, 0);
        sts_A(sbase, av);
        CP_ASYNC_WAIT0();
        __syncthreads();
    }

    const int NT = D_CAT / BK;   // 24
    for (int t = 0; t < NT; t++) {
        const uint32_t sb  = sbase + (t & 1) * BUF_BYTES;
        const uint32_t nxt = sbase + ((t + 1) & 1) * BUF_BYTES;
        const bool has_next = (t + 1 < NT);

        float4 av[2];
        if (has_next) {
            issue_B(nxt, (t + 1) * BK);
            CP_ASYNC_COMMIT();
            ldg_A(av, (t + 1) * BK);
        }

        // ---- compute tile t ----
        #pragma unroll
        for (int ks = 0; ks < 2; ks++) {
            uint32_t ahi[2][4], alo[2][4];
            #pragma unroll
            for (int i = 0; i < 2; i++) {
                uint32_t base = sb + (uint32_t)((wm * 32 + i * 16 + g) * ROWB + ks * 32 + q * 4);
                ahi[i][0] = lds32(base + OFF_A_HI);
                ahi[i][1] = lds32(base + OFF_A_HI + 8 * ROWB);
                ahi[i][2] = lds32(base + OFF_A_HI + 16);
                ahi[i][3] = lds32(base + OFF_A_HI + 8 * ROWB + 16);
                alo[i][0] = lds32(base + OFF_A_LO);
                alo[i][1] = lds32(base + OFF_A_LO + 8 * ROWB);
                alo[i][2] = lds32(base + OFF_A_LO + 16);
                alo[i][3] = lds32(base + OFF_A_LO + 8 * ROWB + 16);
            }
            #pragma unroll
            for (int j = 0; j < 8; j++) {
                uint32_t bb = sb + (uint32_t)((wn * 64 + j * 8 + g) * ROWB + ks * 32 + q * 4);
                uint32_t bhi[2], blo[2];
                bhi[0] = lds32(bb + OFF_B_HI);
                bhi[1] = lds32(bb + OFF_B_HI + 16);
                blo[0] = lds32(bb + OFF_B_LO);
                blo[1] = lds32(bb + OFF_B_LO + 16);
                #pragma unroll
                for (int i = 0; i < 2; i++) {
                    mma16816(acc[i][j], ahi[i], bhi);
                    mma16816(acc[i][j], ahi[i], blo);
                    mma16816(acc[i][j], alo[i], bhi);
                }
            }
        }

        if (has_next) {
            sts_A(nxt, av);
            CP_ASYNC_WAIT0();
        }
        __syncthreads();
    }

    // ---- epilogue: write accumulators ----
    #pragma unroll
    for (int i = 0; i < 2; i++) {
        int row0 = bm + wm * 32 + i * 16 + g;
        int row1 = row0 + 8;
        #pragma unroll
        for (int j = 0; j < 8; j++) {
            int col = wn * 64 + j * 8 + 2 * q;
            if (row0 < M)
                *(float2*)(C + (size_t)row0 * 256 + col) = make_float2(acc[i][j][0], acc[i][j][1]);
            if (row1 < M)
                *(float2*)(C + (size_t)row1 * 256 + col) = make_float2(acc[i][j][2], acc[i][j][3]);
        }
    }
}

// ---------------------------------------------------------------------------
// Launch. Input order (metadata): h, m1, m2, id1, id2, id3, id4, W
// ---------------------------------------------------------------------------
extern "C" void kernel_launch(void* const* d_in, const int* in_sizes, int n_in,
                              void* d_out, int out_size) {
    const float* h  = (const float*)d_in[0];
    const float* m1 = (const float*)d_in[1];
    const float* m2 = (const float*)d_in[2];
    const int* id1  = (const int*)d_in[3];
    const int* id2  = (const int*)d_in[4];
    const int* id3  = (const int*)d_in[5];
    const int* id4  = (const int*)d_in[6];
    const float* W  = (const float*)d_in[7];
    float* out      = (float*)d_out;

    const int nAtoms = in_sizes[0] / D_ATOM;   // 100000
    const int nEdges = in_sizes[3];            // 800000

    // 1) zero x12 scratch
    {
        size_t total = (size_t)nAtoms * (D_X12 / 4);
        int threads = 256;
        int blocks = (int)((total + threads - 1) / threads);
        init_x12_kernel<<<blocks, threads>>>(nAtoms);
    }
    // 1b) W transpose + bf16 split
    {
        int total = 256 * 768;
        prep_w_kernel<<<(total + 255) / 256, 256>>>(W);
    }
    // 2) scatter edges, destination-tiled in 2 L2-resident halves
    {
        size_t total = (size_t)nEdges * 32;
        int threads = 256;
        int blocks = (int)((total + threads - 1) / threads);
        int mid = nAtoms / 2;
        scatter_half_kernel<<<blocks, threads>>>(m1, m2, id1, id2, id3, id4,
                                                 nEdges, 0, mid);
        scatter_half_kernel<<<blocks, threads>>>(m1, m2, id1, id2, id3, id4,
                                                 nEdges, mid, nAtoms);
    }
    // 3) tensor-core GEMM (mma.sync bf16 split-3)
    {
        cudaFuncSetAttribute(gemm_mma_kernel,
                             cudaFuncAttributeMaxDynamicSharedMemorySize,
                             GEMM_SMEM);
        int grid = (nAtoms + 127) / 128;   // 782
        gemm_mma_kernel<<<grid, 512, GEMM_SMEM>>>(h, out, nAtoms);
    }
}

// round 7
// speedup vs baseline: 1.0213x; 1.0213x over previous
#include <cuda_runtime.h>
#include <cuda_bf16.h>
#include <cstdint>

// Problem constants (fixed by the dataset)
#define D_ATOM 256
#define D_EDGE 256
#define D_CAT  768          // 2*D_EDGE + D_ATOM
#define D_X12  512
#define MAX_ATOMS 100000
#define MAX_EDGES 800000

// CSR buckets: j=0 -> id1 (+, m1), j=1 -> id2 (+, m2),
//              j=2 -> id3 (-, m1), j=3 -> id4 (-, m2)
__device__ int g_cnt[4 * MAX_ATOMS];
__device__ int g_base[4 * MAX_ATOMS];
__device__ int g_cursor[4 * MAX_ATOMS];
__device__ int g_list[4 * MAX_EDGES];
__device__ int g_bsum[512];

// W transposed + split into bf16 hi/lo: Wt[n][k] = W[k][n]
__device__ __nv_bfloat16 g_Wt_hi[256 * 768];
__device__ __nv_bfloat16 g_Wt_lo[256 * 768];

// ============================================================================
// small PTX helpers (legal on compute_103)
// ============================================================================
__device__ __forceinline__ uint32_t smem_u32(const void* p) {
    uint32_t a;
    asm("{ .reg .u64 t; cvta.to.shared.u64 t, %1; cvt.u32.u64 %0, t; }"
        : "=r"(a) : "l"(p));
    return a;
}
__device__ __forceinline__ uint32_t lds32(uint32_t a) {
    uint32_t v;
    asm volatile("ld.shared.b32 %0, [%1];" : "=r"(v) : "r"(a));
    return v;
}
__device__ __forceinline__ void sts128(uint32_t a, uint32_t x, uint32_t y,
                                       uint32_t z, uint32_t w) {
    asm volatile("st.shared.v4.b32 [%0], {%1, %2, %3, %4};"
                 :: "r"(a), "r"(x), "r"(y), "r"(z), "r"(w) : "memory");
}
#define CP_ASYNC_16(saddr, gptr) \
    asm volatile("cp.async.cg.shared.global [%0], [%1], 16;" \
                 :: "r"(saddr), "l"(gptr) : "memory")
#define CP_ASYNC_COMMIT() asm volatile("cp.async.commit_group;" ::: "memory")
#define CP_ASYNC_WAIT0()  asm volatile("cp.async.wait_group 0;" ::: "memory")

// bf16 MMA: D(16x8,f32) += A(16x16,bf16,row) * B(16x8,bf16,col)
__device__ __forceinline__ void mma16816(float* c, const uint32_t* a, const uint32_t* b) {
    asm volatile(
        "mma.sync.aligned.m16n8k16.row.col.f32.bf16.bf16.f32 "
        "{%0,%1,%2,%3}, {%4,%5,%6,%7}, {%8,%9}, {%0,%1,%2,%3};"
        : "+f"(c[0]), "+f"(c[1]), "+f"(c[2]), "+f"(c[3])
        : "r"(a[0]), "r"(a[1]), "r"(a[2]), "r"(a[3]), "r"(b[0]), "r"(b[1]));
}

// ---------------------------------------------------------------------------
// CSR build kernels
// ---------------------------------------------------------------------------
__global__ void zero_cnt_kernel(int n) {
    int gid = blockIdx.x * blockDim.x + threadIdx.x;
    if (gid < n) g_cnt[gid] = 0;
}

__global__ void count_kernel(const int* __restrict__ id1,
                             const int* __restrict__ id2,
                             const int* __restrict__ id3,
                             const int* __restrict__ id4,
                             int nEdges, int nAtoms) {
    int e = blockIdx.x * blockDim.x + threadIdx.x;
    if (e >= nEdges) return;
    atomicAdd(&g_cnt[0 * nAtoms + __ldg(id1 + e)], 1);
    atomicAdd(&g_cnt[1 * nAtoms + __ldg(id2 + e)], 1);
    atomicAdd(&g_cnt[2 * nAtoms + __ldg(id3 + e)], 1);
    atomicAdd(&g_cnt[3 * nAtoms + __ldg(id4 + e)], 1);
}

// Hillis-Steele per-block exclusive scan, block = 1024
__global__ void scan1_kernel(int N) {
    __shared__ int sh[1024];
    int tid = threadIdx.x;
    int i = blockIdx.x * 1024 + tid;
    int v = (i < N) ? g_cnt[i] : 0;
    sh[tid] = v;
    __syncthreads();
    #pragma unroll
    for (int off = 1; off < 1024; off <<= 1) {
        int t = (tid >= off) ? sh[tid - off] : 0;
        __syncthreads();
        sh[tid] += t;
        __syncthreads();
    }
    if (i < N) g_base[i] = sh[tid] - v;   // exclusive within block
    if (tid == 1023) g_bsum[blockIdx.x] = sh[1023];
}

__global__ void scan2_kernel(int nb) {
    if (threadIdx.x == 0 && blockIdx.x == 0) {
        int s = 0;
        for (int i = 0; i < nb; i++) { int v = g_bsum[i]; g_bsum[i] = s; s += v; }
    }
}

__global__ void scan3_kernel(int N) {
    int i = blockIdx.x * blockDim.x + threadIdx.x;
    if (i >= N) return;
    int b = g_base[i] + g_bsum[i >> 10];
    g_base[i] = b;
    g_cursor[i] = b;
}

__global__ void fill_kernel(const int* __restrict__ id1,
                            const int* __restrict__ id2,
                            const int* __restrict__ id3,
                            const int* __restrict__ id4,
                            int nEdges, int nAtoms) {
    int e = blockIdx.x * blockDim.x + threadIdx.x;
    if (e >= nEdges) return;
    int p;
    p = atomicAdd(&g_cursor[0 * nAtoms + __ldg(id1 + e)], 1); g_list[p] = e;
    p = atomicAdd(&g_cursor[1 * nAtoms + __ldg(id2 + e)], 1); g_list[p] = e;
    p = atomicAdd(&g_cursor[2 * nAtoms + __ldg(id3 + e)], 1); g_list[p] = e;
    p = atomicAdd(&g_cursor[3 * nAtoms + __ldg(id4 + e)], 1); g_list[p] = e;
}

// ---------------------------------------------------------------------------
// W transpose + bf16 split
// ---------------------------------------------------------------------------
__global__ void prep_w_kernel(const float* __restrict__ W) {
    int gid = blockIdx.x * blockDim.x + threadIdx.x;
    if (gid >= 256 * 768) return;
    int n = gid / 768;
    int k = gid % 768;
    float w = W[(size_t)k * 256 + n];
    __nv_bfloat16 hi = __float2bfloat16_rn(w);
    __nv_bfloat16 lo = __float2bfloat16_rn(w - __bfloat162float(hi));
    g_Wt_hi[gid] = hi;
    g_Wt_lo[gid] = lo;
}

// ---------------------------------------------------------------------------
// Fused gather + mma.sync bf16 split-3 GEMM:
//   C[M,256] = [x1 | x2 | h][M,768] @ W[768,256]
//   where x1/x2 rows are gathered on the fly from m1/m2 via CSR lists.
//   CTA: 128 atoms x full N=256, 512 threads (16 warps, 4x4).
//   K-tiles of 32, double-buffered SMEM; per tile 3 products
//   (Ahi*Bhi, Ahi*Blo, Alo*Bhi), fp32 accumulate.
// ---------------------------------------------------------------------------
#define BK 32
#define ROWB 80                       // smem row stride bytes (64B data + 16 pad)
#define OFF_A_HI 0
#define OFF_A_LO 10240                // 128*80
#define OFF_B_HI 20480
#define OFF_B_LO 40960                // +256*80
#define BUF_BYTES 61440
#define GEMM_SMEM (2 * BUF_BYTES)     // 122880

__device__ __forceinline__ void split2(float a, float b, uint32_t& hi, uint32_t& lo) {
    __nv_bfloat16 ha = __float2bfloat16_rn(a);
    __nv_bfloat16 hb = __float2bfloat16_rn(b);
    __nv_bfloat16 la = __float2bfloat16_rn(a - __bfloat162float(ha));
    __nv_bfloat16 lb = __float2bfloat16_rn(b - __bfloat162float(hb));
    hi = (uint32_t)__bfloat16_as_ushort(ha) | ((uint32_t)__bfloat16_as_ushort(hb) << 16);
    lo = (uint32_t)__bfloat16_as_ushort(la) | ((uint32_t)__bfloat16_as_ushort(lb) << 16);
}

__global__ __launch_bounds__(512, 1)
void gemm_fused_kernel(const float* __restrict__ h,
                       const float* __restrict__ m1,
                       const float* __restrict__ m2,
                       float* __restrict__ C, int M) {
    extern __shared__ char smem[];
    const uint32_t sbase = smem_u32(smem);

    const int tid = threadIdx.x;
    const int wid = tid >> 5;
    const int lid = tid & 31;
    const int wm = wid >> 2;          // 0..3  (M group of 32 rows)
    const int wn = wid & 3;           // 0..3  (N group of 64 cols)
    const int g = lid >> 2;           // 0..7
    const int q4 = lid & 3;           // 0..3
    const int bm = blockIdx.x * 128;

    // gather thread mapping: atom = tid>>2, 8-col group = tid&3
    const int ga = tid >> 2;          // 0..127
    const int gq = tid & 3;           // 0..3
    const int gm_row = bm + ga;

    float acc[2][8][4];
    #pragma unroll
    for (int i = 0; i < 2; i++)
        #pragma unroll
        for (int j = 0; j < 8; j++)
            #pragma unroll
            for (int r = 0; r < 4; r++) acc[i][j][r] = 0.f;

    auto issue_B = [&](uint32_t dstbuf, int k0) {
        #pragma unroll
        for (int it = 0; it < 4; it++) {
            int idx = tid + it * 512;
            int hf = idx >> 10;
            int n = (idx >> 2) & 255;
            int f = idx & 3;
            const __nv_bfloat16* src = (hf ? g_Wt_lo : g_Wt_hi) + (size_t)n * D_CAT + k0 + f * 8;
            uint32_t dst = dstbuf + (hf ? OFF_B_LO : OFF_B_HI) + n * ROWB + f * 16;
            CP_ASYNC_16(dst, src);
        }
    };

    // gather/load one A chunk (32 cols starting at k0) into 8 registers
    auto gather_A = [&](float* a8, int k0) {
        #pragma unroll
        for (int i = 0; i < 8; i++) a8[i] = 0.f;
        if (gm_row >= M) return;
        if (k0 >= D_X12) {
            // h region: direct load
            const float* src = h + (size_t)gm_row * D_ATOM + (k0 - D_X12) + gq * 8;
            float4 u = *(const float4*)src;
            float4 v = *(const float4*)(src + 4);
            a8[0] = u.x; a8[1] = u.y; a8[2] = u.z; a8[3] = u.w;
            a8[4] = v.x; a8[5] = v.y; a8[6] = v.z; a8[7] = v.w;
            return;
        }
        const float* msrc;
        int jp, jm, kk;
        if (k0 < 256) { msrc = m1; jp = 0; jm = 2; kk = k0; }
        else          { msrc = m2; jp = 1; jm = 3; kk = k0 - 256; }
        int bp = jp * M + gm_row;
        int bn = jm * M + gm_row;
        int s0 = __ldg(g_base + bp), e0 = s0 + __ldg(g_cnt + bp);
        int s1 = __ldg(g_base + bn), e1 = s1 + __ldg(g_cnt + bn);
        const float* col = msrc + kk + gq * 8;
        for (int p = s0; p < e0; p++) {
            int e = __ldg(g_list + p);
            const float* r = col + (size_t)e * D_EDGE;
            float4 u = *(const float4*)r;
            float4 v = *(const float4*)(r + 4);
            a8[0] += u.x; a8[1] += u.y; a8[2] += u.z; a8[3] += u.w;
            a8[4] += v.x; a8[5] += v.y; a8[6] += v.z; a8[7] += v.w;
        }
        for (int p = s1; p < e1; p++) {
            int e = __ldg(g_list + p);
            const float* r = col + (size_t)e * D_EDGE;
            float4 u = *(const float4*)r;
            float4 v = *(const float4*)(r + 4);
            a8[0] -= u.x; a8[1] -= u.y; a8[2] -= u.z; a8[3] -= u.w;
            a8[4] -= v.x; a8[5] -= v.y; a8[6] -= v.z; a8[7] -= v.w;
        }
    };

    auto sts_A = [&](uint32_t dstbuf, const float* a8) {
        uint32_t h0, l0, h1, l1, h2, l2, h3, l3;
        split2(a8[0], a8[1], h0, l0);
        split2(a8[2], a8[3], h1, l1);
        split2(a8[4], a8[5], h2, l2);
        split2(a8[6], a8[7], h3, l3);
        uint32_t off = ga * ROWB + gq * 16;
        sts128(dstbuf + OFF_A_HI + off, h0, h1, h2, h3);
        sts128(dstbuf + OFF_A_LO + off, l0, l1, l2, l3);
    };

    // ---- prologue: tile 0 ----
    {
        float a8[8];
        issue_B(sbase, 0);
        CP_ASYNC_COMMIT();
        gather_A(a8, 0);
        sts_A(sbase, a8);
        CP_ASYNC_WAIT0();
        __syncthreads();
    }

    const int NT = D_CAT / BK;   // 24
    for (int t = 0; t < NT; t++) {
        const uint32_t sb  = sbase + (t & 1) * BUF_BYTES;
        const uint32_t nxt = sbase + ((t + 1) & 1) * BUF_BYTES;
        const bool has_next = (t + 1 < NT);

        float a8[8];
        if (has_next) {
            issue_B(nxt, (t + 1) * BK);
            CP_ASYNC_COMMIT();
            gather_A(a8, (t + 1) * BK);
        }

        // ---- compute tile t ----
        #pragma unroll
        for (int ks = 0; ks < 2; ks++) {
            uint32_t ahi[2][4], alo[2][4];
            #pragma unroll
            for (int i = 0; i < 2; i++) {
                uint32_t base = sb + (uint32_t)((wm * 32 + i * 16 + g) * ROWB + ks * 32 + q4 * 4);
                ahi[i][0] = lds32(base + OFF_A_HI);
                ahi[i][1] = lds32(base + OFF_A_HI + 8 * ROWB);
                ahi[i][2] = lds32(base + OFF_A_HI + 16);
                ahi[i][3] = lds32(base + OFF_A_HI + 8 * ROWB + 16);
                alo[i][0] = lds32(base + OFF_A_LO);
                alo[i][1] = lds32(base + OFF_A_LO + 8 * ROWB);
                alo[i][2] = lds32(base + OFF_A_LO + 16);
                alo[i][3] = lds32(base + OFF_A_LO + 8 * ROWB + 16);
            }
            #pragma unroll
            for (int j = 0; j < 8; j++) {
                uint32_t bb = sb + (uint32_t)((wn * 64 + j * 8 + g) * ROWB + ks * 32 + q4 * 4);
                uint32_t bhi[2], blo[2];
                bhi[0] = lds32(bb + OFF_B_HI);
                bhi[1] = lds32(bb + OFF_B_HI + 16);
                blo[0] = lds32(bb + OFF_B_LO);
                blo[1] = lds32(bb + OFF_B_LO + 16);
                #pragma unroll
                for (int i = 0; i < 2; i++) {
                    mma16816(acc[i][j], ahi[i], bhi);
                    mma16816(acc[i][j], ahi[i], blo);
                    mma16816(acc[i][j], alo[i], bhi);
                }
            }
        }

        if (has_next) {
            sts_A(nxt, a8);
            CP_ASYNC_WAIT0();
        }
        __syncthreads();
    }

    // ---- epilogue: write accumulators ----
    #pragma unroll
    for (int i = 0; i < 2; i++) {
        int row0 = bm + wm * 32 + i * 16 + g;
        int row1 = row0 + 8;
        #pragma unroll
        for (int j = 0; j < 8; j++) {
            int col = wn * 64 + j * 8 + 2 * q4;
            if (row0 < M)
                *(float2*)(C + (size_t)row0 * 256 + col) = make_float2(acc[i][j][0], acc[i][j][1]);
            if (row1 < M)
                *(float2*)(C + (size_t)row1 * 256 + col) = make_float2(acc[i][j][2], acc[i][j][3]);
        }
    }
}

// ---------------------------------------------------------------------------
// Launch. Input order (metadata): h, m1, m2, id1, id2, id3, id4, W
// ---------------------------------------------------------------------------
extern "C" void kernel_launch(void* const* d_in, const int* in_sizes, int n_in,
                              void* d_out, int out_size) {
    const float* h  = (const float*)d_in[0];
    const float* m1 = (const float*)d_in[1];
    const float* m2 = (const float*)d_in[2];
    const int* id1  = (const int*)d_in[3];
    const int* id2  = (const int*)d_in[4];
    const int* id3  = (const int*)d_in[5];
    const int* id4  = (const int*)d_in[6];
    const float* W  = (const float*)d_in[7];
    float* out      = (float*)d_out;

    const int nAtoms = in_sizes[0] / D_ATOM;   // 100000
    const int nEdges = in_sizes[3];            // 800000
    const int NB = 4 * nAtoms;                 // 400000 buckets

    // --- CSR build ---
    zero_cnt_kernel<<<(NB + 255) / 256, 256>>>(NB);
    count_kernel<<<(nEdges + 255) / 256, 256>>>(id1, id2, id3, id4, nEdges, nAtoms);
    {
        int nb = (NB + 1023) / 1024;           // 391
        scan1_kernel<<<nb, 1024>>>(NB);
        scan2_kernel<<<1, 32>>>(nb);
        scan3_kernel<<<(NB + 255) / 256, 256>>>(NB);
    }
    fill_kernel<<<(nEdges + 255) / 256, 256>>>(id1, id2, id3, id4, nEdges, nAtoms);

    // --- W transpose + bf16 split ---
    prep_w_kernel<<<(256 * 768 + 255) / 256, 256>>>(W);

    // --- fused gather + tensor-core GEMM ---
    cudaFuncSetAttribute(gemm_fused_kernel,
                         cudaFuncAttributeMaxDynamicSharedMemorySize,
                         GEMM_SMEM);
    int grid = (nAtoms + 127) / 128;   // 782
    gemm_fused_kernel<<<grid, 512, GEMM_SMEM>>>(h, m1, m2, out, nAtoms);
}

// round 8
// speedup vs baseline: 1.0718x; 1.0495x over previous
#include <cuda_runtime.h>
#include <cuda_bf16.h>
#include <cstdint>

// Problem constants (fixed by the dataset)
#define D_ATOM 256
#define D_EDGE 256
#define D_CAT  768          // 2*D_EDGE + D_ATOM
#define D_X12  512
#define MAX_ATOMS 100000
#define MAX_EDGES 800000

// Sign-merged CSR buckets: j=0 -> {id1:+, id3:-} over m1,
//                          j=1 -> {id2:+, id4:-} over m2.
// List entries: edge | (sign << 31)
__device__ int g_cnt[2 * MAX_ATOMS];
__device__ int g_base[2 * MAX_ATOMS];
__device__ int g_cursor[2 * MAX_ATOMS];
__device__ int g_list[4 * MAX_EDGES];
__device__ int g_bsum[512];

// W transposed + split into bf16 hi/lo: Wt[n][k] = W[k][n]
__device__ __nv_bfloat16 g_Wt_hi[256 * 768];
__device__ __nv_bfloat16 g_Wt_lo[256 * 768];

// ============================================================================
// small PTX helpers (legal on compute_103)
// ============================================================================
__device__ __forceinline__ uint32_t smem_u32(const void* p) {
    uint32_t a;
    asm("{ .reg .u64 t; cvta.to.shared.u64 t, %1; cvt.u32.u64 %0, t; }"
        : "=r"(a) : "l"(p));
    return a;
}
__device__ __forceinline__ uint32_t lds32(uint32_t a) {
    uint32_t v;
    asm volatile("ld.shared.b32 %0, [%1];" : "=r"(v) : "r"(a));
    return v;
}
__device__ __forceinline__ void sts128(uint32_t a, uint32_t x, uint32_t y,
                                       uint32_t z, uint32_t w) {
    asm volatile("st.shared.v4.b32 [%0], {%1, %2, %3, %4};"
                 :: "r"(a), "r"(x), "r"(y), "r"(z), "r"(w) : "memory");
}
#define CP_ASYNC_16(saddr, gptr) \
    asm volatile("cp.async.cg.shared.global [%0], [%1], 16;" \
                 :: "r"(saddr), "l"(gptr) : "memory")
#define CP_ASYNC_COMMIT() asm volatile("cp.async.commit_group;" ::: "memory")
#define CP_ASYNC_WAIT0()  asm volatile("cp.async.wait_group 0;" ::: "memory")

// bf16 MMA: D(16x8,f32) += A(16x16,bf16,row) * B(16x8,bf16,col)
__device__ __forceinline__ void mma16816(float* c, const uint32_t* a, const uint32_t* b) {
    asm volatile(
        "mma.sync.aligned.m16n8k16.row.col.f32.bf16.bf16.f32 "
        "{%0,%1,%2,%3}, {%4,%5,%6,%7}, {%8,%9}, {%0,%1,%2,%3};"
        : "+f"(c[0]), "+f"(c[1]), "+f"(c[2]), "+f"(c[3])
        : "r"(a[0]), "r"(a[1]), "r"(a[2]), "r"(a[3]), "r"(b[0]), "r"(b[1]));
}

__device__ __forceinline__ float xsgn(float x, uint32_t s) {
    return __uint_as_float(__float_as_uint(x) ^ s);
}

// ---------------------------------------------------------------------------
// CSR build kernels (sign-merged buckets)
// ---------------------------------------------------------------------------
__global__ void zero_cnt_kernel(int n) {
    int gid = blockIdx.x * blockDim.x + threadIdx.x;
    if (gid < n) g_cnt[gid] = 0;
}

__global__ void count_kernel(const int* __restrict__ id1,
                             const int* __restrict__ id2,
                             const int* __restrict__ id3,
                             const int* __restrict__ id4,
                             int nEdges, int nAtoms) {
    int e = blockIdx.x * blockDim.x + threadIdx.x;
    if (e >= nEdges) return;
    atomicAdd(&g_cnt[__ldg(id1 + e)], 1);
    atomicAdd(&g_cnt[__ldg(id3 + e)], 1);
    atomicAdd(&g_cnt[nAtoms + __ldg(id2 + e)], 1);
    atomicAdd(&g_cnt[nAtoms + __ldg(id4 + e)], 1);
}

// per-block inclusive scan (block = 1024) -> exclusive bases + block sums
__global__ void scan1_kernel(int N) {
    __shared__ int sh[1024];
    int tid = threadIdx.x;
    int i = blockIdx.x * 1024 + tid;
    int v = (i < N) ? g_cnt[i] : 0;
    sh[tid] = v;
    __syncthreads();
    #pragma unroll
    for (int off = 1; off < 1024; off <<= 1) {
        int t = (tid >= off) ? sh[tid - off] : 0;
        __syncthreads();
        sh[tid] += t;
        __syncthreads();
    }
    if (i < N) g_base[i] = sh[tid] - v;
    if (tid == 1023) g_bsum[blockIdx.x] = sh[1023];
}

// single-block parallel scan of block sums (nb <= 512)
__global__ void scan2_kernel(int nb) {
    __shared__ int sh[512];
    int tid = threadIdx.x;
    int v = (tid < nb) ? g_bsum[tid] : 0;
    sh[tid] = v;
    __syncthreads();
    #pragma unroll
    for (int off = 1; off < 512; off <<= 1) {
        int t = (tid >= off) ? sh[tid - off] : 0;
        __syncthreads();
        sh[tid] += t;
        __syncthreads();
    }
    if (tid < nb) g_bsum[tid] = sh[tid] - v;   // exclusive
}

__global__ void scan3_kernel(int N) {
    int i = blockIdx.x * blockDim.x + threadIdx.x;
    if (i >= N) return;
    int b = g_base[i] + g_bsum[i >> 10];
    g_base[i] = b;
    g_cursor[i] = b;
}

__global__ void fill_kernel(const int* __restrict__ id1,
                            const int* __restrict__ id2,
                            const int* __restrict__ id3,
                            const int* __restrict__ id4,
                            int nEdges, int nAtoms) {
    int e = blockIdx.x * blockDim.x + threadIdx.x;
    if (e >= nEdges) return;
    int p;
    p = atomicAdd(&g_cursor[__ldg(id1 + e)], 1);          g_list[p] = e;
    p = atomicAdd(&g_cursor[__ldg(id3 + e)], 1);          g_list[p] = e | 0x80000000;
    p = atomicAdd(&g_cursor[nAtoms + __ldg(id2 + e)], 1); g_list[p] = e;
    p = atomicAdd(&g_cursor[nAtoms + __ldg(id4 + e)], 1); g_list[p] = e | 0x80000000;
}

// ---------------------------------------------------------------------------
// W transpose + bf16 split
// ---------------------------------------------------------------------------
__global__ void prep_w_kernel(const float* __restrict__ W) {
    int gid = blockIdx.x * blockDim.x + threadIdx.x;
    if (gid >= 256 * 768) return;
    int n = gid / 768;
    int k = gid % 768;
    float w = W[(size_t)k * 256 + n];
    __nv_bfloat16 hi = __float2bfloat16_rn(w);
    __nv_bfloat16 lo = __float2bfloat16_rn(w - __bfloat162float(hi));
    g_Wt_hi[gid] = hi;
    g_Wt_lo[gid] = lo;
}

// ---------------------------------------------------------------------------
// Fused gather + mma.sync bf16 split-3 GEMM.
// ---------------------------------------------------------------------------
#define BK 32
#define ROWB 80
#define OFF_A_HI 0
#define OFF_A_LO 10240
#define OFF_B_HI 20480
#define OFF_B_LO 40960
#define BUF_BYTES 61440
#define GEMM_SMEM (2 * BUF_BYTES)

__device__ __forceinline__ void split2(float a, float b, uint32_t& hi, uint32_t& lo) {
    __nv_bfloat16 ha = __float2bfloat16_rn(a);
    __nv_bfloat16 hb = __float2bfloat16_rn(b);
    __nv_bfloat16 la = __float2bfloat16_rn(a - __bfloat162float(ha));
    __nv_bfloat16 lb = __float2bfloat16_rn(b - __bfloat162float(hb));
    hi = (uint32_t)__bfloat16_as_ushort(ha) | ((uint32_t)__bfloat16_as_ushort(hb) << 16);
    lo = (uint32_t)__bfloat16_as_ushort(la) | ((uint32_t)__bfloat16_as_ushort(lb) << 16);
}

__device__ __forceinline__ void acc8(float* a8, float4 u, float4 v, uint32_t s) {
    a8[0] += xsgn(u.x, s); a8[1] += xsgn(u.y, s);
    a8[2] += xsgn(u.z, s); a8[3] += xsgn(u.w, s);
    a8[4] += xsgn(v.x, s); a8[5] += xsgn(v.y, s);
    a8[6] += xsgn(v.z, s); a8[7] += xsgn(v.w, s);
}

__global__ __launch_bounds__(512, 1)
void gemm_fused_kernel(const float* __restrict__ h,
                       const float* __restrict__ m1,
                       const float* __restrict__ m2,
                       float* __restrict__ C, int M) {
    extern __shared__ char smem[];
    const uint32_t sbase = smem_u32(smem);

    const int tid = threadIdx.x;
    const int wid = tid >> 5;
    const int lid = tid & 31;
    const int wm = wid >> 2;
    const int wn = wid & 3;
    const int g = lid >> 2;
    const int q4 = lid & 3;
    const int bm = blockIdx.x * 128;

    const int ga = tid >> 2;          // atom within tile, 0..127
    const int gq = tid & 3;           // 8-col group, 0..3
    const int gm_row = bm + ga;

    float acc[2][8][4];
    #pragma unroll
    for (int i = 0; i < 2; i++)
        #pragma unroll
        for (int j = 0; j < 8; j++)
            #pragma unroll
            for (int r = 0; r < 4; r++) acc[i][j][r] = 0.f;

    auto issue_B = [&](uint32_t dstbuf, int k0) {
        #pragma unroll
        for (int it = 0; it < 4; it++) {
            int idx = tid + it * 512;
            int hf = idx >> 10;
            int n = (idx >> 2) & 255;
            int f = idx & 3;
            const __nv_bfloat16* src = (hf ? g_Wt_lo : g_Wt_hi) + (size_t)n * D_CAT + k0 + f * 8;
            uint32_t dst = dstbuf + (hf ? OFF_B_LO : OFF_B_HI) + n * ROWB + f * 16;
            CP_ASYNC_16(dst, src);
        }
    };

    // gather one A chunk (32 cols at k0): batch-4 edges for MLP
    auto gather_A = [&](float* a8, int k0) {
        #pragma unroll
        for (int i = 0; i < 8; i++) a8[i] = 0.f;
        if (gm_row >= M) return;
        if (k0 >= D_X12) {
            const float* src = h + (size_t)gm_row * D_ATOM + (k0 - D_X12) + gq * 8;
            float4 u = __ldg((const float4*)src);
            float4 v = __ldg((const float4*)(src + 4));
            a8[0] = u.x; a8[1] = u.y; a8[2] = u.z; a8[3] = u.w;
            a8[4] = v.x; a8[5] = v.y; a8[6] = v.z; a8[7] = v.w;
            return;
        }
        const float* msrc;
        int b, kk;
        if (k0 < 256) { msrc = m1; b = gm_row;     kk = k0; }
        else          { msrc = m2; b = M + gm_row; kk = k0 - 256; }
        int p   = __ldg(g_base + b);
        int rem = __ldg(g_cnt + b);
        const float* col = msrc + kk + gq * 8;

        while (rem >= 4) {
            int r0 = __ldg(g_list + p);
            int r1 = __ldg(g_list + p + 1);
            int r2 = __ldg(g_list + p + 2);
            int r3 = __ldg(g_list + p + 3);
            const float* q0 = col + (size_t)(r0 & 0x7FFFFFFF) * D_EDGE;
            const float* q1 = col + (size_t)(r1 & 0x7FFFFFFF) * D_EDGE;
            const float* q2 = col + (size_t)(r2 & 0x7FFFFFFF) * D_EDGE;
            const float* q3 = col + (size_t)(r3 & 0x7FFFFFFF) * D_EDGE;
            float4 u0 = __ldg((const float4*)q0);
            float4 u1 = __ldg((const float4*)q1);
            float4 u2 = __ldg((const float4*)q2);
            float4 u3 = __ldg((const float4*)q3);
            float4 v0 = __ldg((const float4*)(q0 + 4));
            float4 v1 = __ldg((const float4*)(q1 + 4));
            float4 v2 = __ldg((const float4*)(q2 + 4));
            float4 v3 = __ldg((const float4*)(q3 + 4));
            acc8(a8, u0, v0, (uint32_t)r0 & 0x80000000u);
            acc8(a8, u1, v1, (uint32_t)r1 & 0x80000000u);
            acc8(a8, u2, v2, (uint32_t)r2 & 0x80000000u);
            acc8(a8, u3, v3, (uint32_t)r3 & 0x80000000u);
            p += 4; rem -= 4;
        }
        while (rem > 0) {
            int r0 = __ldg(g_list + p);
            const float* q0 = col + (size_t)(r0 & 0x7FFFFFFF) * D_EDGE;
            float4 u0 = __ldg((const float4*)q0);
            float4 v0 = __ldg((const float4*)(q0 + 4));
            acc8(a8, u0, v0, (uint32_t)r0 & 0x80000000u);
            p++; rem--;
        }
    };

    auto sts_A = [&](uint32_t dstbuf, const float* a8) {
        uint32_t h0, l0, h1, l1, h2, l2, h3, l3;
        split2(a8[0], a8[1], h0, l0);
        split2(a8[2], a8[3], h1, l1);
        split2(a8[4], a8[5], h2, l2);
        split2(a8[6], a8[7], h3, l3);
        uint32_t off = ga * ROWB + gq * 16;
        sts128(dstbuf + OFF_A_HI + off, h0, h1, h2, h3);
        sts128(dstbuf + OFF_A_LO + off, l0, l1, l2, l3);
    };

    // ---- prologue: tile 0 ----
    {
        float a8[8];
        issue_B(sbase, 0);
        CP_ASYNC_COMMIT();
        gather_A(a8, 0);
        sts_A(sbase, a8);
        CP_ASYNC_WAIT0();
        __syncthreads();
    }

    const int NT = D_CAT / BK;   // 24
    for (int t = 0; t < NT; t++) {
        const uint32_t sb  = sbase + (t & 1) * BUF_BYTES;
        const uint32_t nxt = sbase + ((t + 1) & 1) * BUF_BYTES;
        const bool has_next = (t + 1 < NT);

        float a8[8];
        if (has_next) {
            issue_B(nxt, (t + 1) * BK);
            CP_ASYNC_COMMIT();
            gather_A(a8, (t + 1) * BK);
        }

        #pragma unroll
        for (int ks = 0; ks < 2; ks++) {
            uint32_t ahi[2][4], alo[2][4];
            #pragma unroll
            for (int i = 0; i < 2; i++) {
                uint32_t base = sb + (uint32_t)((wm * 32 + i * 16 + g) * ROWB + ks * 32 + q4 * 4);
                ahi[i][0] = lds32(base + OFF_A_HI);
                ahi[i][1] = lds32(base + OFF_A_HI + 8 * ROWB);
                ahi[i][2] = lds32(base + OFF_A_HI + 16);
                ahi[i][3] = lds32(base + OFF_A_HI + 8 * ROWB + 16);
                alo[i][0] = lds32(base + OFF_A_LO);
                alo[i][1] = lds32(base + OFF_A_LO + 8 * ROWB);
                alo[i][2] = lds32(base + OFF_A_LO + 16);
                alo[i][3] = lds32(base + OFF_A_LO + 8 * ROWB + 16);
            }
            #pragma unroll
            for (int j = 0; j < 8; j++) {
                uint32_t bb = sb + (uint32_t)((wn * 64 + j * 8 + g) * ROWB + ks * 32 + q4 * 4);
                uint32_t bhi[2], blo[2];
                bhi[0] = lds32(bb + OFF_B_HI);
                bhi[1] = lds32(bb + OFF_B_HI + 16);
                blo[0] = lds32(bb + OFF_B_LO);
                blo[1] = lds32(bb + OFF_B_LO + 16);
                #pragma unroll
                for (int i = 0; i < 2; i++) {
                    mma16816(acc[i][j], ahi[i], bhi);
                    mma16816(acc[i][j], ahi[i], blo);
                    mma16816(acc[i][j], alo[i], bhi);
                }
            }
        }

        if (has_next) {
            sts_A(nxt, a8);
            CP_ASYNC_WAIT0();
        }
        __syncthreads();
    }

    // ---- epilogue ----
    #pragma unroll
    for (int i = 0; i < 2; i++) {
        int row0 = bm + wm * 32 + i * 16 + g;
        int row1 = row0 + 8;
        #pragma unroll
        for (int j = 0; j < 8; j++) {
            int col = wn * 64 + j * 8 + 2 * q4;
            if (row0 < M)
                *(float2*)(C + (size_t)row0 * 256 + col) = make_float2(acc[i][j][0], acc[i][j][1]);
            if (row1 < M)
                *(float2*)(C + (size_t)row1 * 256 + col) = make_float2(acc[i][j][2], acc[i][j][3]);
        }
    }
}

// ---------------------------------------------------------------------------
// Launch. Input order (metadata): h, m1, m2, id1, id2, id3, id4, W
// ---------------------------------------------------------------------------
extern "C" void kernel_launch(void* const* d_in, const int* in_sizes, int n_in,
                              void* d_out, int out_size) {
    const float* h  = (const float*)d_in[0];
    const float* m1 = (const float*)d_in[1];
    const float* m2 = (const float*)d_in[2];
    const int* id1  = (const int*)d_in[3];
    const int* id2  = (const int*)d_in[4];
    const int* id3  = (const int*)d_in[5];
    const int* id4  = (const int*)d_in[6];
    const float* W  = (const float*)d_in[7];
    float* out      = (float*)d_out;

    const int nAtoms = in_sizes[0] / D_ATOM;   // 100000
    const int nEdges = in_sizes[3];            // 800000
    const int NB = 2 * nAtoms;                 // 200000 merged buckets

    // --- CSR build (sign-merged) ---
    zero_cnt_kernel<<<(NB + 255) / 256, 256>>>(NB);
    count_kernel<<<(nEdges + 255) / 256, 256>>>(id1, id2, id3, id4, nEdges, nAtoms);
    {
        int nb = (NB + 1023) / 1024;           // 196
        scan1_kernel<<<nb, 1024>>>(NB);
        scan2_kernel<<<1, 512>>>(nb);
        scan3_kernel<<<(NB + 255) / 256, 256>>>(NB);
    }
    fill_kernel<<<(nEdges + 255) / 256, 256>>>(id1, id2, id3, id4, nEdges, nAtoms);

    // --- W transpose + bf16 split ---
    prep_w_kernel<<<(256 * 768 + 255) / 256, 256>>>(W);

    // --- fused gather + tensor-core GEMM ---
    cudaFuncSetAttribute(gemm_fused_kernel,
                         cudaFuncAttributeMaxDynamicSharedMemorySize,
                         GEMM_SMEM);
    int grid = (nAtoms + 127) / 128;   // 782
    gemm_fused_kernel<<<grid, 512, GEMM_SMEM>>>(h, m1, m2, out, nAtoms);
}

// round 9
// speedup vs baseline: 1.5293x; 1.4268x over previous
#include <cuda_runtime.h>
#include <cuda_bf16.h>
#include <cstdint>

// Problem constants (fixed by the dataset)
#define D_ATOM 256
#define D_EDGE 256
#define D_CAT  768          // 2*D_EDGE + D_ATOM
#define D_X12  512
#define MAX_ATOMS 100000
#define MAX_EDGES 800000

// Sign-merged CSR buckets: j=0 -> {id1:+, id3:-} over m1,
//                          j=1 -> {id2:+, id4:-} over m2.
// List entries: edge | (sign << 31)
__device__ int g_cnt[2 * MAX_ATOMS];
__device__ int g_base[2 * MAX_ATOMS];
__device__ int g_cursor[2 * MAX_ATOMS];
__device__ int g_list[4 * MAX_EDGES];
__device__ int g_bsum[512];

// Dense A = [x1 | x2 | h] in bf16 hi/lo split, row-major ld=768 (153.6 MB each)
__device__ __nv_bfloat16 g_xhi[(size_t)MAX_ATOMS * D_CAT];
__device__ __nv_bfloat16 g_xlo[(size_t)MAX_ATOMS * D_CAT];

// W transposed + split into bf16 hi/lo: Wt[n][k] = W[k][n]
__device__ __nv_bfloat16 g_Wt_hi[256 * 768];
__device__ __nv_bfloat16 g_Wt_lo[256 * 768];

// ============================================================================
// small PTX helpers (legal on compute_103)
// ============================================================================
__device__ __forceinline__ uint32_t smem_u32(const void* p) {
    uint32_t a;
    asm("{ .reg .u64 t; cvta.to.shared.u64 t, %1; cvt.u32.u64 %0, t; }"
        : "=r"(a) : "l"(p));
    return a;
}
__device__ __forceinline__ uint32_t lds32(uint32_t a) {
    uint32_t v;
    asm volatile("ld.shared.b32 %0, [%1];" : "=r"(v) : "r"(a));
    return v;
}
#define CP_ASYNC_16(saddr, gptr) \
    asm volatile("cp.async.cg.shared.global [%0], [%1], 16;" \
                 :: "r"(saddr), "l"(gptr) : "memory")
#define CP_ASYNC_16_PRED(saddr, gptr, srcsz) \
    asm volatile("cp.async.cg.shared.global [%0], [%1], 16, %2;" \
                 :: "r"(saddr), "l"(gptr), "r"(srcsz) : "memory")
#define CP_ASYNC_COMMIT() asm volatile("cp.async.commit_group;" ::: "memory")
#define CP_ASYNC_WAIT0()  asm volatile("cp.async.wait_group 0;" ::: "memory")

// bf16 MMA: D(16x8,f32) += A(16x16,bf16,row) * B(16x8,bf16,col)
__device__ __forceinline__ void mma16816(float* c, const uint32_t* a, const uint32_t* b) {
    asm volatile(
        "mma.sync.aligned.m16n8k16.row.col.f32.bf16.bf16.f32 "
        "{%0,%1,%2,%3}, {%4,%5,%6,%7}, {%8,%9}, {%0,%1,%2,%3};"
        : "+f"(c[0]), "+f"(c[1]), "+f"(c[2]), "+f"(c[3])
        : "r"(a[0]), "r"(a[1]), "r"(a[2]), "r"(a[3]), "r"(b[0]), "r"(b[1]));
}

__device__ __forceinline__ float xsgn(float x, uint32_t s) {
    return __uint_as_float(__float_as_uint(x) ^ s);
}

// ---------------------------------------------------------------------------
// CSR build kernels (sign-merged buckets)
// ---------------------------------------------------------------------------
__global__ void zero_cnt_kernel(int n) {
    int gid = blockIdx.x * blockDim.x + threadIdx.x;
    if (gid < n) g_cnt[gid] = 0;
}

__global__ void count_kernel(const int* __restrict__ id1,
                             const int* __restrict__ id2,
                             const int* __restrict__ id3,
                             const int* __restrict__ id4,
                             int nEdges, int nAtoms) {
    int e = blockIdx.x * blockDim.x + threadIdx.x;
    if (e >= nEdges) return;
    atomicAdd(&g_cnt[__ldg(id1 + e)], 1);
    atomicAdd(&g_cnt[__ldg(id3 + e)], 1);
    atomicAdd(&g_cnt[nAtoms + __ldg(id2 + e)], 1);
    atomicAdd(&g_cnt[nAtoms + __ldg(id4 + e)], 1);
}

__global__ void scan1_kernel(int N) {
    __shared__ int sh[1024];
    int tid = threadIdx.x;
    int i = blockIdx.x * 1024 + tid;
    int v = (i < N) ? g_cnt[i] : 0;
    sh[tid] = v;
    __syncthreads();
    #pragma unroll
    for (int off = 1; off < 1024; off <<= 1) {
        int t = (tid >= off) ? sh[tid - off] : 0;
        __syncthreads();
        sh[tid] += t;
        __syncthreads();
    }
    if (i < N) g_base[i] = sh[tid] - v;
    if (tid == 1023) g_bsum[blockIdx.x] = sh[1023];
}

__global__ void scan2_kernel(int nb) {
    __shared__ int sh[512];
    int tid = threadIdx.x;
    int v = (tid < nb) ? g_bsum[tid] : 0;
    sh[tid] = v;
    __syncthreads();
    #pragma unroll
    for (int off = 1; off < 512; off <<= 1) {
        int t = (tid >= off) ? sh[tid - off] : 0;
        __syncthreads();
        sh[tid] += t;
        __syncthreads();
    }
    if (tid < nb) g_bsum[tid] = sh[tid] - v;
}

__global__ void scan3_kernel(int N) {
    int i = blockIdx.x * blockDim.x + threadIdx.x;
    if (i >= N) return;
    int b = g_base[i] + g_bsum[i >> 10];
    g_base[i] = b;
    g_cursor[i] = b;
}

__global__ void fill_kernel(const int* __restrict__ id1,
                            const int* __restrict__ id2,
                            const int* __restrict__ id3,
                            const int* __restrict__ id4,
                            int nEdges, int nAtoms) {
    int e = blockIdx.x * blockDim.x + threadIdx.x;
    if (e >= nEdges) return;
    int p;
    p = atomicAdd(&g_cursor[__ldg(id1 + e)], 1);          g_list[p] = e;
    p = atomicAdd(&g_cursor[__ldg(id3 + e)], 1);          g_list[p] = e | 0x80000000;
    p = atomicAdd(&g_cursor[nAtoms + __ldg(id2 + e)], 1); g_list[p] = e;
    p = atomicAdd(&g_cursor[nAtoms + __ldg(id4 + e)], 1); g_list[p] = e | 0x80000000;
}

// ---------------------------------------------------------------------------
// prep kernels: W transpose + split; h split into dense A tail
// ---------------------------------------------------------------------------
__global__ void prep_w_kernel(const float* __restrict__ W) {
    int gid = blockIdx.x * blockDim.x + threadIdx.x;
    if (gid >= 256 * 768) return;
    int n = gid / 768;
    int k = gid % 768;
    float w = W[(size_t)k * 256 + n];
    __nv_bfloat16 hi = __float2bfloat16_rn(w);
    __nv_bfloat16 lo = __float2bfloat16_rn(w - __bfloat162float(hi));
    g_Wt_hi[gid] = hi;
    g_Wt_lo[gid] = lo;
}

__device__ __forceinline__ void split2(float a, float b, uint32_t& hi, uint32_t& lo) {
    __nv_bfloat16 ha = __float2bfloat16_rn(a);
    __nv_bfloat16 hb = __float2bfloat16_rn(b);
    __nv_bfloat16 la = __float2bfloat16_rn(a - __bfloat162float(ha));
    __nv_bfloat16 lb = __float2bfloat16_rn(b - __bfloat162float(hb));
    hi = (uint32_t)__bfloat16_as_ushort(ha) | ((uint32_t)__bfloat16_as_ushort(hb) << 16);
    lo = (uint32_t)__bfloat16_as_ushort(la) | ((uint32_t)__bfloat16_as_ushort(lb) << 16);
}

__global__ void prep_h_kernel(const float* __restrict__ h, int nAtoms) {
    size_t gid = (size_t)blockIdx.x * blockDim.x + threadIdx.x;
    size_t total = (size_t)nAtoms * 64;   // one float4 per thread
    if (gid >= total) return;
    int a = (int)(gid >> 6);
    int c = (int)(gid & 63);
    float4 v = __ldg((const float4*)(h + (size_t)a * D_ATOM + c * 4));
    uint32_t h0, l0, h1, l1;
    split2(v.x, v.y, h0, l0);
    split2(v.z, v.w, h1, l1);
    size_t off = (size_t)a * D_CAT + D_X12 + c * 4;
    *(uint2*)(g_xhi + off) = make_uint2(h0, h1);
    *(uint2*)(g_xlo + off) = make_uint2(l0, l1);
}

// ---------------------------------------------------------------------------
// Gather kernel: x12[a] = sum of +/- m rows per CSR bucket, written as
// bf16 hi/lo split into the dense A buffers. Thread = (atom, 4-col group);
// 64 threads cooperate on one atom, walking the bucket ONCE and reading
// full 1KB edge rows coalesced. No atomics, sequential stores.
// ---------------------------------------------------------------------------
__global__ __launch_bounds__(256)
void gather_kernel(const float* __restrict__ m1,
                   const float* __restrict__ m2,
                   int nAtoms) {
    int tid = threadIdx.x;
    int a = blockIdx.x * 4 + (tid >> 6);
    int c = tid & 63;                 // float4 col group: cols c*4..c*4+3
    if (a >= nAtoms) return;

    #pragma unroll
    for (int j = 0; j < 2; j++) {
        const float* msrc = j ? m2 : m1;
        int b = j * nAtoms + a;
        int p   = __ldg(g_base + b);
        int rem = __ldg(g_cnt + b);
        const float* col = msrc + c * 4;

        float4 s = make_float4(0.f, 0.f, 0.f, 0.f);
        while (rem >= 4) {
            int r0 = __ldg(g_list + p);
            int r1 = __ldg(g_list + p + 1);
            int r2 = __ldg(g_list + p + 2);
            int r3 = __ldg(g_list + p + 3);
            float4 u0 = __ldg((const float4*)(col + (size_t)(r0 & 0x7FFFFFFF) * D_EDGE));
            float4 u1 = __ldg((const float4*)(col + (size_t)(r1 & 0x7FFFFFFF) * D_EDGE));
            float4 u2 = __ldg((const float4*)(col + (size_t)(r2 & 0x7FFFFFFF) * D_EDGE));
            float4 u3 = __ldg((const float4*)(col + (size_t)(r3 & 0x7FFFFFFF) * D_EDGE));
            uint32_t s0 = (uint32_t)r0 & 0x80000000u;
            uint32_t s1 = (uint32_t)r1 & 0x80000000u;
            uint32_t s2 = (uint32_t)r2 & 0x80000000u;
            uint32_t s3 = (uint32_t)r3 & 0x80000000u;
            s.x += xsgn(u0.x, s0); s.y += xsgn(u0.y, s0);
            s.z += xsgn(u0.z, s0); s.w += xsgn(u0.w, s0);
            s.x += xsgn(u1.x, s1); s.y += xsgn(u1.y, s1);
            s.z += xsgn(u1.z, s1); s.w += xsgn(u1.w, s1);
            s.x += xsgn(u2.x, s2); s.y += xsgn(u2.y, s2);
            s.z += xsgn(u2.z, s2); s.w += xsgn(u2.w, s2);
            s.x += xsgn(u3.x, s3); s.y += xsgn(u3.y, s3);
            s.z += xsgn(u3.z, s3); s.w += xsgn(u3.w, s3);
            p += 4; rem -= 4;
        }
        while (rem > 0) {
            int r0 = __ldg(g_list + p);
            float4 u0 = __ldg((const float4*)(col + (size_t)(r0 & 0x7FFFFFFF) * D_EDGE));
            uint32_t s0 = (uint32_t)r0 & 0x80000000u;
            s.x += xsgn(u0.x, s0); s.y += xsgn(u0.y, s0);
            s.z += xsgn(u0.z, s0); s.w += xsgn(u0.w, s0);
            p++; rem--;
        }

        uint32_t h0, l0, h1, l1;
        split2(s.x, s.y, h0, l0);
        split2(s.z, s.w, h1, l1);
        size_t off = (size_t)a * D_CAT + j * 256 + c * 4;
        *(uint2*)(g_xhi + off) = make_uint2(h0, h1);
        *(uint2*)(g_xlo + off) = make_uint2(l0, l1);
    }
}

// ---------------------------------------------------------------------------
// GEMM: C[M,256] = A[M,768] @ W[768,256], A/B in bf16 hi/lo split.
// 3 products per tile: Ahi*Bhi + Ahi*Blo + Alo*Bhi, fp32 accumulate.
// CTA: 128 rows x full N=256, 512 threads (16 warps 4x4), K-tiles of 32,
// double-buffered SMEM, all loads via cp.async.
// ---------------------------------------------------------------------------
#define BK 32
#define ROWB 80
#define OFF_A_HI 0
#define OFF_A_LO 10240
#define OFF_B_HI 20480
#define OFF_B_LO 40960
#define BUF_BYTES 61440
#define GEMM_SMEM (2 * BUF_BYTES)

__global__ __launch_bounds__(512, 1)
void gemm_mma_kernel(float* __restrict__ C, int M) {
    extern __shared__ char smem[];
    const uint32_t sbase = smem_u32(smem);

    const int tid = threadIdx.x;
    const int wid = tid >> 5;
    const int lid = tid & 31;
    const int wm = wid >> 2;
    const int wn = wid & 3;
    const int g = lid >> 2;
    const int q4 = lid & 3;
    const int bm = blockIdx.x * 128;

    float acc[2][8][4];
    #pragma unroll
    for (int i = 0; i < 2; i++)
        #pragma unroll
        for (int j = 0; j < 8; j++)
            #pragma unroll
            for (int r = 0; r < 4; r++) acc[i][j][r] = 0.f;

    auto issue_AB = [&](uint32_t dstbuf, int k0) {
        // A: 1024 16B chunks (hi/lo x 128 rows x 4)
        #pragma unroll
        for (int it = 0; it < 2; it++) {
            int idx = tid + it * 512;
            int hf = idx >> 9;
            int m = (idx >> 2) & 127;
            int f = idx & 3;
            int gm = bm + m;
            int ok = (gm < M);
            const __nv_bfloat16* base = hf ? g_xlo : g_xhi;
            const __nv_bfloat16* src = base + (size_t)(ok ? gm : 0) * D_CAT + k0 + f * 8;
            uint32_t dst = dstbuf + (hf ? OFF_A_LO : OFF_A_HI) + m * ROWB + f * 16;
            CP_ASYNC_16_PRED(dst, src, ok ? 16 : 0);
        }
        // B: 2048 16B chunks (hi/lo x 256 rows x 4)
        #pragma unroll
        for (int it = 0; it < 4; it++) {
            int idx = tid + it * 512;
            int hf = idx >> 10;
            int n = (idx >> 2) & 255;
            int f = idx & 3;
            const __nv_bfloat16* src = (hf ? g_Wt_lo : g_Wt_hi) + (size_t)n * D_CAT + k0 + f * 8;
            uint32_t dst = dstbuf + (hf ? OFF_B_LO : OFF_B_HI) + n * ROWB + f * 16;
            CP_ASYNC_16(dst, src);
        }
    };

    // prologue
    issue_AB(sbase, 0);
    CP_ASYNC_COMMIT();
    CP_ASYNC_WAIT0();
    __syncthreads();

    const int NT = D_CAT / BK;   // 24
    for (int t = 0; t < NT; t++) {
        const uint32_t sb  = sbase + (t & 1) * BUF_BYTES;
        const uint32_t nxt = sbase + ((t + 1) & 1) * BUF_BYTES;
        const bool has_next = (t + 1 < NT);

        if (has_next) {
            issue_AB(nxt, (t + 1) * BK);
            CP_ASYNC_COMMIT();
        }

        #pragma unroll
        for (int ks = 0; ks < 2; ks++) {
            uint32_t ahi[2][4], alo[2][4];
            #pragma unroll
            for (int i = 0; i < 2; i++) {
                uint32_t base = sb + (uint32_t)((wm * 32 + i * 16 + g) * ROWB + ks * 32 + q4 * 4);
                ahi[i][0] = lds32(base + OFF_A_HI);
                ahi[i][1] = lds32(base + OFF_A_HI + 8 * ROWB);
                ahi[i][2] = lds32(base + OFF_A_HI + 16);
                ahi[i][3] = lds32(base + OFF_A_HI + 8 * ROWB + 16);
                alo[i][0] = lds32(base + OFF_A_LO);
                alo[i][1] = lds32(base + OFF_A_LO + 8 * ROWB);
                alo[i][2] = lds32(base + OFF_A_LO + 16);
                alo[i][3] = lds32(base + OFF_A_LO + 8 * ROWB + 16);
            }
            #pragma unroll
            for (int j = 0; j < 8; j++) {
                uint32_t bb = sb + (uint32_t)((wn * 64 + j * 8 + g) * ROWB + ks * 32 + q4 * 4);
                uint32_t bhi[2], blo[2];
                bhi[0] = lds32(bb + OFF_B_HI);
                bhi[1] = lds32(bb + OFF_B_HI + 16);
                blo[0] = lds32(bb + OFF_B_LO);
                blo[1] = lds32(bb + OFF_B_LO + 16);
                #pragma unroll
                for (int i = 0; i < 2; i++) {
                    mma16816(acc[i][j], ahi[i], bhi);
                    mma16816(acc[i][j], ahi[i], blo);
                    mma16816(acc[i][j], alo[i], bhi);
                }
            }
        }

        if (has_next) CP_ASYNC_WAIT0();
        __syncthreads();
    }

    // epilogue
    #pragma unroll
    for (int i = 0; i < 2; i++) {
        int row0 = bm + wm * 32 + i * 16 + g;
        int row1 = row0 + 8;
        #pragma unroll
        for (int j = 0; j < 8; j++) {
            int col = wn * 64 + j * 8 + 2 * q4;
            if (row0 < M)
                *(float2*)(C + (size_t)row0 * 256 + col) = make_float2(acc[i][j][0], acc[i][j][1]);
            if (row1 < M)
                *(float2*)(C + (size_t)row1 * 256 + col) = make_float2(acc[i][j][2], acc[i][j][3]);
        }
    }
}

// ---------------------------------------------------------------------------
// Launch. Input order (metadata): h, m1, m2, id1, id2, id3, id4, W
// ---------------------------------------------------------------------------
extern "C" void kernel_launch(void* const* d_in, const int* in_sizes, int n_in,
                              void* d_out, int out_size) {
    const float* h  = (const float*)d_in[0];
    const float* m1 = (const float*)d_in[1];
    const float* m2 = (const float*)d_in[2];
    const int* id1  = (const int*)d_in[3];
    const int* id2  = (const int*)d_in[4];
    const int* id3  = (const int*)d_in[5];
    const int* id4  = (const int*)d_in[6];
    const float* W  = (const float*)d_in[7];
    float* out      = (float*)d_out;

    const int nAtoms = in_sizes[0] / D_ATOM;   // 100000
    const int nEdges = in_sizes[3];            // 800000
    const int NB = 2 * nAtoms;                 // 200000 merged buckets

    // --- CSR build (sign-merged) ---
    zero_cnt_kernel<<<(NB + 255) / 256, 256>>>(NB);
    count_kernel<<<(nEdges + 255) / 256, 256>>>(id1, id2, id3, id4, nEdges, nAtoms);
    {
        int nb = (NB + 1023) / 1024;           // 196
        scan1_kernel<<<nb, 1024>>>(NB);
        scan2_kernel<<<1, 512>>>(nb);
        scan3_kernel<<<(NB + 255) / 256, 256>>>(NB);
    }
    fill_kernel<<<(nEdges + 255) / 256, 256>>>(id1, id2, id3, id4, nEdges, nAtoms);

    // --- prep: W split (indep) + h split into dense A tail ---
    prep_w_kernel<<<(256 * 768 + 255) / 256, 256>>>(W);
    {
        size_t total = (size_t)nAtoms * 64;
        prep_h_kernel<<<(int)((total + 255) / 256), 256>>>(h, nAtoms);
    }

    // --- gather x12 into dense A (bf16 split), no atomics ---
    gather_kernel<<<(nAtoms + 3) / 4, 256>>>(m1, m2, nAtoms);

    // --- tensor-core GEMM ---
    cudaFuncSetAttribute(gemm_mma_kernel,
                         cudaFuncAttributeMaxDynamicSharedMemorySize,
                         GEMM_SMEM);
    int grid = (nAtoms + 127) / 128;   // 782
    gemm_mma_kernel<<<grid, 512, GEMM_SMEM>>>(out, nAtoms);
}